// round 1
// baseline (speedup 1.0000x reference)
#include <cuda_runtime.h>
#include <cuda_bf16.h>
#include <math_constants.h>

// Problem constants (fixed by the dataset)
#define NN   50000
#define EE   600000
#define GG   1000
#define HID  128
#define INF_ 64
#define EPS  1e-5f
#define SLOPE 0.01f

// ---------------------------------------------------------------------------
// Scratch (static __device__ arrays; no allocation anywhere)
// ---------------------------------------------------------------------------
__device__ float g_hs [NN * HID];   // (x@W) * cs[row]
__device__ float g_agg[NN * HID];   // scatter target, then y = agg*cd in place
__device__ float g_h  [NN * HID];   // layer output (normalized + leaky)
__device__ float g_cs [NN];
__device__ float g_cd [NN];
__device__ int   g_deg[2 * NN];     // [0..N): outdeg(src), [N..2N): indeg(dst)
__device__ float g_stats[2 * HID];  // col sum, col sumsq
__device__ float g_ab   [2 * HID];  // alpha, beta
__device__ int   g_gstart[GG + 1];

__device__ __forceinline__ float leaky(float v) { return v > 0.f ? v : SLOPE * v; }

// ---------------------------------------------------------------------------
// Utility: zero a buffer (float4 granularity)
// ---------------------------------------------------------------------------
__global__ void k_zero(float4* p, int n4) {
    int i = blockIdx.x * blockDim.x + threadIdx.x;
    if (i < n4) p[i] = make_float4(0.f, 0.f, 0.f, 0.f);
}

// ---------------------------------------------------------------------------
// Degrees from edge list
// ---------------------------------------------------------------------------
__global__ void k_degrees(const int* __restrict__ src, const int* __restrict__ dst,
                          int* __restrict__ deg) {
    int e = blockIdx.x * blockDim.x + threadIdx.x;
    if (e >= EE) return;
    atomicAdd(&deg[src[e]], 1);
    atomicAdd(&deg[NN + dst[e]], 1);
}

__global__ void k_invdeg(const int* __restrict__ deg,
                         float* __restrict__ cs, float* __restrict__ cd) {
    int i = blockIdx.x * blockDim.x + threadIdx.x;
    if (i >= NN) return;
    cs[i] = rsqrtf(fmaxf((float)deg[i], 1.f));
    cd[i] = rsqrtf(fmaxf((float)deg[NN + i], 1.f));
}

// ---------------------------------------------------------------------------
// Graph segment starts (graph_ids sorted ascending)
// ---------------------------------------------------------------------------
__global__ void k_gstart(const int* __restrict__ gid, int* __restrict__ gstart) {
    int i = blockIdx.x * blockDim.x + threadIdx.x;
    if (i >= NN) return;
    int g  = gid[i];
    int gp = (i == 0) ? -1 : gid[i - 1];
    for (int gg = gp + 1; gg <= g; gg++) gstart[gg] = i;
    if (i == NN - 1)
        for (int gg = g + 1; gg <= GG; gg++) gstart[gg] = NN;
}

// ---------------------------------------------------------------------------
// GEMM: out[N,128] = (X[N,K] @ W[K,128]) * cs[row]
// Block: 64 rows x 128 cols, 256 threads, 8x4 micro-tile, BK=32 chunks.
// ---------------------------------------------------------------------------
template <int K>
__global__ void __launch_bounds__(256, 2)
k_gemm_cs(const float* __restrict__ X, const float* __restrict__ W,
          const float* __restrict__ cs, float* __restrict__ out, int nrows) {
    constexpr int BK = 32;
    __shared__ float Ws[BK][HID];
    __shared__ float Xs[64][BK];

    int tid = threadIdx.x;
    int tx = tid & 31, ty = tid >> 5;
    int row0 = blockIdx.x * 64;
    int rb = ty * 8, cb = tx * 4;

    float acc[8][4];
#pragma unroll
    for (int i = 0; i < 8; i++)
#pragma unroll
        for (int j = 0; j < 4; j++) acc[i][j] = 0.f;

    for (int k0 = 0; k0 < K; k0 += BK) {
        // load W chunk [BK][128]
        for (int i = tid; i < BK * 32; i += 256) {
            int k = i >> 5, c = (i & 31) * 4;
            *(float4*)&Ws[k][c] = *(const float4*)&W[(k0 + k) * HID + c];
        }
        // load X chunk [64][BK]
        for (int i = tid; i < 64 * (BK / 4); i += 256) {
            int r = i / (BK / 4), k4 = (i % (BK / 4)) * 4;
            int g = row0 + r;
            float4 v = (g < nrows) ? *(const float4*)&X[(size_t)g * K + k0 + k4]
                                   : make_float4(0.f, 0.f, 0.f, 0.f);
            *(float4*)&Xs[r][k4] = v;
        }
        __syncthreads();

#pragma unroll
        for (int k = 0; k < BK; k += 4) {
            float xv[8][4];
#pragma unroll
            for (int i = 0; i < 8; i++)
                *(float4*)xv[i] = *(const float4*)&Xs[rb + i][k];
#pragma unroll
            for (int kk = 0; kk < 4; kk++) {
                float4 w = *(const float4*)&Ws[k + kk][cb];
#pragma unroll
                for (int i = 0; i < 8; i++) {
                    float x = xv[i][kk];
                    acc[i][0] += x * w.x;
                    acc[i][1] += x * w.y;
                    acc[i][2] += x * w.z;
                    acc[i][3] += x * w.w;
                }
            }
        }
        __syncthreads();
    }

#pragma unroll
    for (int i = 0; i < 8; i++) {
        int g = row0 + rb + i;
        if (g < nrows) {
            float c = __ldg(&cs[g]);
            float4 o = make_float4(acc[i][0] * c, acc[i][1] * c,
                                   acc[i][2] * c, acc[i][3] * c);
            *(float4*)&out[(size_t)g * HID + cb] = o;
        }
    }
}

// ---------------------------------------------------------------------------
// Edge scatter: warp per edge, vector reduction add (v4.f32)
// ---------------------------------------------------------------------------
__global__ void k_scatter(const float* __restrict__ hs,
                          const int* __restrict__ src, const int* __restrict__ dst,
                          float* __restrict__ agg) {
    int w = (blockIdx.x * blockDim.x + threadIdx.x) >> 5;
    if (w >= EE) return;
    int lane = threadIdx.x & 31;
    int s = __ldg(&src[w]);
    int d = __ldg(&dst[w]);
    float4 v = __ldg((const float4*)(hs + (size_t)s * HID) + lane);
    float* q = agg + (size_t)d * HID + lane * 4;
    asm volatile("red.global.add.v4.f32 [%0], {%1, %2, %3, %4};"
                 :: "l"(q), "f"(v.x), "f"(v.y), "f"(v.z), "f"(v.w)
                 : "memory");
}

// ---------------------------------------------------------------------------
// y = agg * cd  (in place), plus column sum & sumsq into stats
// blockDim 256: channel = tid&127, row-phase = tid>>7
// ---------------------------------------------------------------------------
__global__ void k_colstats(float* __restrict__ agg, const float* __restrict__ cd,
                           float* __restrict__ stats) {
    const int ROWS = 256;
    int c = threadIdx.x & 127;
    int half = threadIdx.x >> 7;
    int base = blockIdx.x * ROWS;
    int end = min(base + ROWS, NN);
    float s = 0.f, s2 = 0.f;
    for (int r = base + half; r < end; r += 2) {
        float v = agg[(size_t)r * HID + c] * __ldg(&cd[r]);
        agg[(size_t)r * HID + c] = v;
        s += v;
        s2 += v * v;
    }
    atomicAdd(&stats[c], s);
    atomicAdd(&stats[HID + c], s2);
}

// ---------------------------------------------------------------------------
// Per-channel alpha/beta from stats:
//  out = (y - s*m) * rsqrt(var+eps) * w + b  ==  y*alpha + beta
//  var = E[y^2] - m^2 * (2s - s^2)
// ---------------------------------------------------------------------------
__global__ void k_alpha_beta(const float* __restrict__ stats,
                             const float* __restrict__ gw, const float* __restrict__ gb,
                             const float* __restrict__ gs, float* __restrict__ ab) {
    int c = threadIdx.x;
    float m   = stats[c] * (1.f / (float)NN);
    float ex2 = stats[HID + c] * (1.f / (float)NN);
    float s   = gs[c];
    float var = ex2 - m * m * (2.f * s - s * s);
    float inv = rsqrtf(var + EPS);
    float a   = inv * gw[c];
    ab[c]       = a;
    ab[HID + c] = gb[c] - s * m * a;
}

// ---------------------------------------------------------------------------
// h = leaky(y*alpha + beta), vectorized
// ---------------------------------------------------------------------------
__global__ void k_norm_leaky(const float* __restrict__ y, const float* __restrict__ ab,
                             float* __restrict__ h) {
    int idx = blockIdx.x * blockDim.x + threadIdx.x;   // one float4 each
    if (idx >= NN * (HID / 4)) return;
    int j = idx & 31;                                   // float4 index in row
    float4 v = *(const float4*)(y + (size_t)idx * 4);
    float4 a = __ldg((const float4*)ab + j);
    float4 b = __ldg((const float4*)ab + 32 + j);
    float4 o;
    o.x = leaky(v.x * a.x + b.x);
    o.y = leaky(v.y * a.y + b.y);
    o.z = leaky(v.z * a.z + b.z);
    o.w = leaky(v.w * a.w + b.w);
    *(float4*)(h + (size_t)idx * 4) = o;
}

// ---------------------------------------------------------------------------
// Readout: block per graph, thread per channel. mean|max|min, final leaky.
// ---------------------------------------------------------------------------
__global__ void k_readout(const float* __restrict__ h, const int* __restrict__ gstart,
                          float* __restrict__ out, int layer) {
    int g = blockIdx.x;
    int c = threadIdx.x;
    int s0 = gstart[g], s1 = gstart[g + 1];
    float sum = 0.f, mx = -CUDART_INF_F, mn = CUDART_INF_F;
    for (int r = s0; r < s1; r++) {
        float v = __ldg(&h[(size_t)r * HID + c]);
        sum += v;
        mx = fmaxf(mx, v);
        mn = fminf(mn, v);
    }
    int cnt = s1 - s0;
    float mean = sum / fmaxf((float)cnt, 1.f);
    if (cnt == 0) { mx = 0.f; mn = 0.f; }
    float* o = out + (size_t)g * (9 * HID) + layer * (3 * HID);
    o[c]           = leaky(mean);
    o[HID + c]     = leaky(mx);
    o[2 * HID + c] = leaky(mn);
}

// ---------------------------------------------------------------------------
// Launch
// ---------------------------------------------------------------------------
extern "C" void kernel_launch(void* const* d_in, const int* in_sizes, int n_in,
                              void* d_out, int out_size) {
    const float* X   = (const float*)d_in[0];
    const float* W1  = (const float*)d_in[1];
    const float* W2  = (const float*)d_in[2];
    const float* W3  = (const float*)d_in[3];
    const float* gw  = (const float*)d_in[4];
    const float* gb  = (const float*)d_in[5];
    const float* gs  = (const float*)d_in[6];
    const int*   src = (const int*)d_in[7];
    const int*   dst = (const int*)d_in[8];
    const int*   gid = (const int*)d_in[9];
    float* out = (float*)d_out;

    float *hs, *agg, *h, *cs, *cd, *stats, *ab;
    int *deg, *gstart;
    cudaGetSymbolAddress((void**)&hs,     g_hs);
    cudaGetSymbolAddress((void**)&agg,    g_agg);
    cudaGetSymbolAddress((void**)&h,      g_h);
    cudaGetSymbolAddress((void**)&cs,     g_cs);
    cudaGetSymbolAddress((void**)&cd,     g_cd);
    cudaGetSymbolAddress((void**)&stats,  g_stats);
    cudaGetSymbolAddress((void**)&ab,     g_ab);
    cudaGetSymbolAddress((void**)&deg,    g_deg);
    cudaGetSymbolAddress((void**)&gstart, g_gstart);

    // --- setup: degrees + segment starts ---
    k_zero<<<(2 * NN / 4 + 255) / 256, 256>>>((float4*)deg, 2 * NN / 4);
    k_degrees<<<(EE + 255) / 256, 256>>>(src, dst, deg);
    k_invdeg<<<(NN + 255) / 256, 256>>>(deg, cs, cd);
    k_gstart<<<(NN + 255) / 256, 256>>>(gid, gstart);

    const float* Wl[3] = {W1, W2, W3};
    const int gemm_grid = (NN + 63) / 64;
    const int agg4 = NN * HID / 4;

    for (int L = 0; L < 3; L++) {
        // 1) hs = (x @ W) * cs
        if (L == 0)
            k_gemm_cs<INF_><<<gemm_grid, 256>>>(X, Wl[L], cs, hs, NN);
        else
            k_gemm_cs<HID><<<gemm_grid, 256>>>(h, Wl[L], cs, hs, NN);

        // 2) agg = 0 ; scatter-add over edges
        k_zero<<<(agg4 + 255) / 256, 256>>>((float4*)agg, agg4);
        k_scatter<<<(EE * 32 + 255) / 256, 256>>>(hs, src, dst, agg);

        // 3) y = agg*cd in place + column stats
        k_zero<<<1, 64>>>((float4*)stats, 2 * HID / 4);
        k_colstats<<<(NN + 255) / 256, 256>>>(agg, cd, stats);

        // 4) per-channel alpha/beta, then h = leaky(y*alpha+beta)
        k_alpha_beta<<<1, HID>>>(stats, gw + L * HID, gb + L * HID, gs + L * HID, ab);
        k_norm_leaky<<<(NN * (HID / 4) + 255) / 256, 256>>>(agg, ab, h);

        // 5) per-graph readout into output slice
        k_readout<<<GG, HID>>>(h, gstart, out, L);
    }
}